// round 9
// baseline (speedup 1.0000x reference)
#include <cuda_runtime.h>
#include <cuda_bf16.h>
#include <math.h>

#define BATCH   16384
#define ENCD    512
#define HD      256
#define GD      1024
#define TSTEPS  64
#define MROWS   64
#define NTHR    512
#define HROW    264     // padded h row length (bf16 elems)
#define HROWB   528     // bytes
#define WROWB   80      // padded W buffer row bytes (40 bf16)

// shared memory byte offsets
#define HBYTES  33792   // 64*264*2
#define WBOFF   135168  // 4*HBYTES
#define WBUFSZ  20480   // 256*40*2
#define VOFF    217088  // WBOFF + 4*WBUFSZ
#define UOFF    221184
#define WREDOFF 225280
#define YOFF    226304
#define PARTOFF 226560
#define SMEMSZ  227584

// v[j] = W_emb @ W_k[:,j] ; u[j] = b_emb @ W_k[:,j] + b_lstm[j]
__device__ float g_v[GD];
__device__ float g_u[GD];
// W_r split to bf16 hi/lo, transposed to [N][K] and permuted:
// row' = p*256 + g*64 + w64  <->  n = g*256 + p*64 + w64  (pass p streams rows p*256..p*256+255)
__device__ __nv_bfloat16 g_whi[GD * HD];
__device__ __nv_bfloat16 g_wlo[GD * HD];

__global__ void precompute_vu_kernel(const float* __restrict__ W_emb,
                                     const float* __restrict__ b_emb,
                                     const float* __restrict__ W_k,
                                     const float* __restrict__ b_lstm) {
    int j = blockIdx.x * blockDim.x + threadIdx.x;
    if (j < GD) {
        float v = 0.f, u = 0.f;
        #pragma unroll
        for (int d = 0; d < 32; ++d) {
            float wk = W_k[d * GD + j];
            v += W_emb[d] * wk;
            u += b_emb[d] * wk;
        }
        g_v[j] = v;
        g_u[j] = u + b_lstm[j];
    }
}

__global__ void precompute_w_kernel(const float* __restrict__ W_r) {
    int idx = blockIdx.x * blockDim.x + threadIdx.x;   // 0 .. GD*HD-1
    if (idx < GD * HD) {
        int row = idx >> 8;          // row' 0..1023
        int k   = idx & 255;
        int p   = row >> 8;
        int rem = row & 255;
        int g   = rem >> 6;
        int w64 = rem & 63;
        int n   = g * 256 + p * 64 + w64;
        float val = W_r[(size_t)k * GD + n];
        __nv_bfloat16 hi = __float2bfloat16(val);
        __nv_bfloat16 lo = __float2bfloat16(val - __bfloat162float(hi));
        g_whi[idx] = hi;
        g_wlo[idx] = lo;
    }
}

__device__ __forceinline__ float sigmoidf_(float x) {
    return __fdividef(1.f, 1.f + __expf(-x));
}
__device__ __forceinline__ float tanh_fast(float x) {
    float e = __expf(-2.f * x);
    return __fdividef(1.f - e, 1.f + e);
}

__device__ __forceinline__ void cp16(void* dst, const void* src) {
    unsigned s = (unsigned)__cvta_generic_to_shared(dst);
    asm volatile("cp.async.cg.shared.global [%0], [%1], 16;" :: "r"(s), "l"(src));
}

__device__ __forceinline__ void ldm_x4(unsigned* r, unsigned addr) {
    asm volatile("ldmatrix.sync.aligned.m8n8.x4.shared.b16 {%0,%1,%2,%3}, [%4];"
                 : "=r"(r[0]), "=r"(r[1]), "=r"(r[2]), "=r"(r[3]) : "r"(addr));
}

__device__ __forceinline__ void mma_bf16(float* d, const unsigned* a, const unsigned* b) {
    asm volatile("mma.sync.aligned.m16n8k16.row.col.f32.bf16.bf16.f32 "
                 "{%0,%1,%2,%3}, {%4,%5,%6,%7}, {%8,%9}, {%0,%1,%2,%3};"
                 : "+f"(d[0]), "+f"(d[1]), "+f"(d[2]), "+f"(d[3])
                 : "r"(a[0]), "r"(a[1]), "r"(a[2]), "r"(a[3]), "r"(b[0]), "r"(b[1]));
}

// stage W chunk c (0..31): pass p = c>>3, k-chunk kc = c&7, into parity buffer c&1.
// Buffer rows padded to 80B; each thread moves 2x16B for hi and lo.
__device__ __forceinline__ void stage_w(char* smem, int c, int tid) {
    int p = c >> 3, kc = c & 7, par = c & 1;
    int rr = tid >> 1, hq = tid & 1;
    size_t src = (size_t)(p * 256 + rr) * HD + kc * 32 + hq * 16;
    char* dst = smem + WBOFF + par * (2 * WBUFSZ) + rr * WROWB + hq * 32;
    cp16(dst,                g_whi + src);
    cp16(dst + 16,           g_whi + src + 8);
    cp16(dst + WBUFSZ,       g_wlo + src);
    cp16(dst + WBUFSZ + 16,  g_wlo + src + 8);
}

// CTA = 64 rows for all 64 steps. 16 warps = 4 row-groups (m16) x 4 col-quads.
// Per pass p (64 h-cols): warp (rg,q) computes 16 rows x 16 h-cols x 4 gates via
// mma.sync m16n8k16 bf16 split-3 (fp32 accum). c-state in regs, h double-buffered
// bf16 hi/lo in smem, W streamed from pre-split globals via cp.async.
__global__ void __launch_bounds__(NTHR, 1)
lstm_decode_kernel(const float* __restrict__ enc,
                   const float* __restrict__ finalx,
                   const float* __restrict__ W_enc,
                   const float* __restrict__ b_enc,
                   const float* __restrict__ W_red,
                   const float* __restrict__ b_red,
                   float* __restrict__ out)
{
    extern __shared__ char smem[];
    float* shv    = (float*)(smem + VOFF);
    float* shu    = (float*)(smem + UOFF);
    float* shwred = (float*)(smem + WREDOFF);
    float* shy    = (float*)(smem + YOFF);
    float* shpart = (float*)(smem + PARTOFF);

    const int tid = threadIdx.x;
    const int w   = tid >> 5;
    const int l   = tid & 31;
    const int rg  = w >> 2;
    const int q   = w & 3;
    const int row0 = blockIdx.x * MROWS;

    for (int i = tid; i < GD; i += NTHR) { shv[i] = g_v[i]; shu[i] = g_u[i]; }
    for (int i = tid; i < HD; i += NTHR) shwred[i] = W_red[i];
    if (tid < MROWS) shy[tid] = finalx[row0 + tid];
    const float bred = __ldg(b_red);

    // ---- h0 = enc @ W_enc + b_enc  ([64,512]@[512,256], scalar fp32) ----
    {
        float* senc = (float*)(smem + WBOFF);            // [64][32]
        float* swe  = (float*)(smem + WBOFF + 8192);     // [32][256]
        float a[4][8];
        #pragma unroll
        for (int r = 0; r < 4; ++r)
            #pragma unroll
            for (int c = 0; c < 8; ++c) a[r][c] = 0.f;

        for (int k0 = 0; k0 < ENCD; k0 += 32) {
            __syncthreads();
            { int r = tid >> 3, c4 = (tid & 7) * 4;
              *(float4*)(senc + r * 32 + c4) =
                  *(const float4*)(enc + (size_t)(row0 + r) * ENCD + k0 + c4); }
            #pragma unroll
            for (int s = 0; s < 4; ++s) {
                int slot = tid + s * NTHR;
                int kk = slot >> 6, c4 = (slot & 63) * 4;
                *(float4*)(swe + kk * 256 + c4) =
                    *(const float4*)(W_enc + (size_t)(k0 + kk) * HD + c4);
            }
            __syncthreads();
            #pragma unroll
            for (int kk = 0; kk < 32; ++kk) {
                float av[4];
                #pragma unroll
                for (int r = 0; r < 4; ++r) av[r] = senc[(4 * w + r) * 32 + kk];
                float4 b0 = *(const float4*)(swe + kk * 256 + l * 8);
                float4 b1 = *(const float4*)(swe + kk * 256 + l * 8 + 4);
                #pragma unroll
                for (int r = 0; r < 4; ++r) {
                    a[r][0] += av[r] * b0.x; a[r][1] += av[r] * b0.y;
                    a[r][2] += av[r] * b0.z; a[r][3] += av[r] * b0.w;
                    a[r][4] += av[r] * b1.x; a[r][5] += av[r] * b1.y;
                    a[r][6] += av[r] * b1.z; a[r][7] += av[r] * b1.w;
                }
            }
        }
        __syncthreads();   // swe reads done before wbuf reuse below
        __nv_bfloat16* hh = (__nv_bfloat16*)(smem);
        __nv_bfloat16* hl = (__nv_bfloat16*)(smem + HBYTES);
        #pragma unroll
        for (int r = 0; r < 4; ++r)
            #pragma unroll
            for (int c = 0; c < 8; ++c) {
                float val = a[r][c] + __ldg(b_enc + l * 8 + c);
                __nv_bfloat16 hi = __float2bfloat16(val);
                hh[(4 * w + r) * HROW + l * 8 + c] = hi;
                hl[(4 * w + r) * HROW + l * 8 + c] =
                    __float2bfloat16(val - __bfloat162float(hi));
            }
    }

    // prologue: stage W chunk 0
    stage_w(smem, 0, tid);
    asm volatile("cp.async.commit_group;");

    const unsigned smem_sh = (unsigned)__cvta_generic_to_shared(smem);
    // A (h) ldmatrix address: row = rg*16 + (l&15), k-half = l>>4
    const unsigned a_off = (rg * 16 + (l & 15)) * HROWB + (l >> 4) * 16;
    // B (W) ldmatrix address within a version buffer: nrow = q*16 + (l&7) + ((l>>4)<<3)
    const unsigned b_off = (q * 16 + (l & 7) + ((l >> 4) << 3)) * WROWB + ((l >> 3) & 1) * 16;
    const int r0 = rg * 16 + (l >> 2);
    const int r1 = r0 + 8;

    float cst[4][2][2][2];
    #pragma unroll
    for (int p = 0; p < 4; ++p)
        #pragma unroll
        for (int j = 0; j < 2; ++j) {
            cst[p][j][0][0] = 0.f; cst[p][j][0][1] = 0.f;
            cst[p][j][1][0] = 0.f; cst[p][j][1][1] = 0.f;
        }

    for (int t = 0; t < TSTEPS; ++t) {
        const unsigned hcur = smem_sh + (unsigned)(t & 1) * (2 * HBYTES);
        const unsigned ahib = hcur + a_off;
        const unsigned alob = hcur + HBYTES + a_off;
        __nv_bfloat16* hn_hi = (__nv_bfloat16*)(smem + ((t + 1) & 1) * (2 * HBYTES));
        __nv_bfloat16* hn_lo = (__nv_bfloat16*)(smem + ((t + 1) & 1) * (2 * HBYTES) + HBYTES);
        float yd0 = 0.f, yd1 = 0.f;

        #pragma unroll
        for (int p = 0; p < 4; ++p) {
            float acc[4][2][4];
            #pragma unroll
            for (int g = 0; g < 4; ++g)
                #pragma unroll
                for (int j = 0; j < 2; ++j) {
                    acc[g][j][0] = 0.f; acc[g][j][1] = 0.f;
                    acc[g][j][2] = 0.f; acc[g][j][3] = 0.f;
                }

            #pragma unroll 1
            for (int kc = 0; kc < 8; ++kc) {
                int c = p * 8 + kc;
                stage_w(smem, (c + 1) & 31, tid);
                asm volatile("cp.async.commit_group;");
                asm volatile("cp.async.wait_group 1;");
                __syncthreads();                         // chunk c visible to all

                unsigned wb = smem_sh + WBOFF + (unsigned)(kc & 1) * (2 * WBUFSZ);
                #pragma unroll
                for (int s = 0; s < 2; ++s) {
                    unsigned ahi[4], alo[4];
                    unsigned ak = (unsigned)(kc * 64 + s * 32);
                    ldm_x4(ahi, ahib + ak);
                    ldm_x4(alo, alob + ak);
                    #pragma unroll
                    for (int g = 0; g < 4; ++g) {
                        unsigned bhi[4], blo[4];
                        unsigned baddr = wb + (unsigned)(g * 64 * WROWB) + b_off + s * 32;
                        ldm_x4(bhi, baddr);
                        ldm_x4(blo, baddr + WBUFSZ);
                        mma_bf16(acc[g][0], ahi, bhi + 0);
                        mma_bf16(acc[g][1], ahi, bhi + 2);
                        mma_bf16(acc[g][0], ahi, blo + 0);
                        mma_bf16(acc[g][1], ahi, blo + 2);
                        mma_bf16(acc[g][0], alo, bhi + 0);
                        mma_bf16(acc[g][1], alo, bhi + 2);
                    }
                }
                __syncthreads();                         // consumption done before restage
            }

            // ---- epilogue for pass p (warp-local gates) ----
            float yp0 = shy[r0], yp1 = shy[r1];
            #pragma unroll
            for (int j = 0; j < 2; ++j)
                #pragma unroll
                for (int cp = 0; cp < 2; ++cp) {
                    int hcol = p * 64 + q * 16 + j * 8 + (l & 3) * 2 + cp;
                    float vi = shv[hcol],          ui = shu[hcol];
                    float vf = shv[HD + hcol],     uf = shu[HD + hcol];
                    float vc = shv[2 * HD + hcol], uc = shu[2 * HD + hcol];
                    float vo = shv[3 * HD + hcol], uo = shu[3 * HD + hcol];
                    float wr = shwred[hcol];
                    #pragma unroll
                    for (int rh = 0; rh < 2; ++rh) {
                        float yy = rh ? yp1 : yp0;
                        int di = rh * 2 + cp;
                        float gi = acc[0][j][di] + yy * vi + ui;
                        float gf = acc[1][j][di] + yy * vf + uf;
                        float gc = acc[2][j][di] + yy * vc + uc;
                        float go = acc[3][j][di] + yy * vo + uo;
                        float cn = sigmoidf_(gf) * cst[p][j][rh][cp]
                                 + sigmoidf_(gi) * tanh_fast(gc);
                        float hn = sigmoidf_(go) * tanh_fast(cn);
                        cst[p][j][rh][cp] = cn;
                        int r = rh ? r1 : r0;
                        __nv_bfloat16 hb = __float2bfloat16(hn);
                        hn_hi[r * HROW + hcol] = hb;
                        hn_lo[r * HROW + hcol] =
                            __float2bfloat16(hn - __bfloat162float(hb));
                        if (rh) yd1 += hn * wr; else yd0 += hn * wr;
                    }
                }
        }

        // ---- y = h_new @ w_red + b_red ----
        yd0 += __shfl_xor_sync(0xffffffffu, yd0, 1);
        yd0 += __shfl_xor_sync(0xffffffffu, yd0, 2);
        yd1 += __shfl_xor_sync(0xffffffffu, yd1, 1);
        yd1 += __shfl_xor_sync(0xffffffffu, yd1, 2);
        if ((l & 3) == 0) {
            shpart[r0 * 4 + q] = yd0;
            shpart[r1 * 4 + q] = yd1;
        }
        __syncthreads();
        if (tid < MROWS) {
            float y = shpart[tid * 4] + shpart[tid * 4 + 1]
                    + shpart[tid * 4 + 2] + shpart[tid * 4 + 3] + bred;
            shy[tid] = y;
            out[(size_t)(row0 + tid) * TSTEPS + t] = y;
        }
        // next step's chunk-0 __syncthreads orders shy/h writes before reads
    }
    asm volatile("cp.async.wait_group 0;");
}

extern "C" void kernel_launch(void* const* d_in, const int* in_sizes, int n_in,
                              void* d_out, int out_size) {
    const float* enc    = (const float*)d_in[0];
    const float* finalx = (const float*)d_in[1];
    const float* W_emb  = (const float*)d_in[2];
    const float* b_emb  = (const float*)d_in[3];
    const float* W_enc  = (const float*)d_in[4];
    const float* b_enc  = (const float*)d_in[5];
    const float* W_k    = (const float*)d_in[6];
    const float* W_r    = (const float*)d_in[7];
    const float* b_lstm = (const float*)d_in[8];
    const float* W_red  = (const float*)d_in[9];
    const float* b_red  = (const float*)d_in[10];
    float* out = (float*)d_out;

    cudaFuncSetAttribute(lstm_decode_kernel,
                         cudaFuncAttributeMaxDynamicSharedMemorySize, SMEMSZ);

    precompute_vu_kernel<<<1, 1024>>>(W_emb, b_emb, W_k, b_lstm);
    precompute_w_kernel<<<512, 512>>>(W_r);
    lstm_decode_kernel<<<BATCH / MROWS, NTHR, SMEMSZ>>>(
        enc, finalx, W_enc, b_enc, W_red, b_red, out);
}

// round 10
// speedup vs baseline: 1.0008x; 1.0008x over previous
#include <cuda_runtime.h>
#include <cuda_bf16.h>
#include <math.h>

#define BATCH   16384
#define ENCD    512
#define HD      256
#define GD      1024
#define TSTEPS  64
#define MROWS   64
#define NTHR    512
#define HROW    264     // padded h row length (bf16 elems)
#define HROWB   528     // bytes
#define WROWB   80      // padded W buffer row bytes (40 bf16)

// shared memory byte offsets
#define HBYTES  33792   // 64*264*2
#define WBOFF   135168  // 4*HBYTES
#define WBUFSZ  20480   // 256*40*2
#define VOFF    217088  // WBOFF + 4*WBUFSZ
#define UOFF    221184
#define WREDOFF 225280
#define YOFF    226304
#define PARTOFF 226560
#define SMEMSZ  227584

// v[j] = W_emb @ W_k[:,j] ; u[j] = b_emb @ W_k[:,j] + b_lstm[j]
__device__ float g_v[GD];
__device__ float g_u[GD];
// W_r split to bf16 hi/lo, transposed to [N][K] and permuted:
// row' = p*256 + g*64 + w64  <->  n = g*256 + p*64 + w64  (pass p streams rows p*256..p*256+255)
__device__ __nv_bfloat16 g_whi[GD * HD];
__device__ __nv_bfloat16 g_wlo[GD * HD];

__global__ void precompute_vu_kernel(const float* __restrict__ W_emb,
                                     const float* __restrict__ b_emb,
                                     const float* __restrict__ W_k,
                                     const float* __restrict__ b_lstm) {
    int j = blockIdx.x * blockDim.x + threadIdx.x;
    if (j < GD) {
        float v = 0.f, u = 0.f;
        #pragma unroll
        for (int d = 0; d < 32; ++d) {
            float wk = W_k[d * GD + j];
            v += W_emb[d] * wk;
            u += b_emb[d] * wk;
        }
        g_v[j] = v;
        g_u[j] = u + b_lstm[j];
    }
}

__global__ void precompute_w_kernel(const float* __restrict__ W_r) {
    int idx = blockIdx.x * blockDim.x + threadIdx.x;   // 0 .. GD*HD-1
    if (idx < GD * HD) {
        int row = idx >> 8;          // row' 0..1023
        int k   = idx & 255;
        int p   = row >> 8;
        int rem = row & 255;
        int g   = rem >> 6;
        int w64 = rem & 63;
        int n   = g * 256 + p * 64 + w64;
        float val = W_r[(size_t)k * GD + n];
        __nv_bfloat16 hi = __float2bfloat16(val);
        __nv_bfloat16 lo = __float2bfloat16(val - __bfloat162float(hi));
        g_whi[idx] = hi;
        g_wlo[idx] = lo;
    }
}

__device__ __forceinline__ float sigmoidf_(float x) {
    return __fdividef(1.f, 1.f + __expf(-x));
}
__device__ __forceinline__ float tanh_fast(float x) {
    float e = __expf(-2.f * x);
    return __fdividef(1.f - e, 1.f + e);
}

__device__ __forceinline__ void cp16(void* dst, const void* src) {
    unsigned s = (unsigned)__cvta_generic_to_shared(dst);
    asm volatile("cp.async.cg.shared.global [%0], [%1], 16;" :: "r"(s), "l"(src));
}

__device__ __forceinline__ void ldm_x4(unsigned* r, unsigned addr) {
    asm volatile("ldmatrix.sync.aligned.m8n8.x4.shared.b16 {%0,%1,%2,%3}, [%4];"
                 : "=r"(r[0]), "=r"(r[1]), "=r"(r[2]), "=r"(r[3]) : "r"(addr));
}

__device__ __forceinline__ void mma_bf16(float* d, const unsigned* a, const unsigned* b) {
    asm volatile("mma.sync.aligned.m16n8k16.row.col.f32.bf16.bf16.f32 "
                 "{%0,%1,%2,%3}, {%4,%5,%6,%7}, {%8,%9}, {%0,%1,%2,%3};"
                 : "+f"(d[0]), "+f"(d[1]), "+f"(d[2]), "+f"(d[3])
                 : "r"(a[0]), "r"(a[1]), "r"(a[2]), "r"(a[3]), "r"(b[0]), "r"(b[1]));
}

// stage W chunk c (0..31): pass p = c>>3, k-chunk kc = c&7, into parity buffer c&1.
// Buffer rows padded to 80B; each thread moves 2x16B for hi and lo.
__device__ __forceinline__ void stage_w(char* smem, int c, int tid) {
    int p = c >> 3, kc = c & 7, par = c & 1;
    int rr = tid >> 1, hq = tid & 1;
    size_t src = (size_t)(p * 256 + rr) * HD + kc * 32 + hq * 16;
    char* dst = smem + WBOFF + par * (2 * WBUFSZ) + rr * WROWB + hq * 32;
    cp16(dst,                g_whi + src);
    cp16(dst + 16,           g_whi + src + 8);
    cp16(dst + WBUFSZ,       g_wlo + src);
    cp16(dst + WBUFSZ + 16,  g_wlo + src + 8);
}

// CTA = 64 rows for all 64 steps. 16 warps = 4 row-groups (m16) x 4 col-quads.
// Per pass p (64 h-cols): warp (rg,q) computes 16 rows x 16 h-cols x 4 gates via
// mma.sync m16n8k16 bf16 split-3 (fp32 accum). c-state in regs, h double-buffered
// bf16 hi/lo in smem, W streamed from pre-split globals via cp.async.
__global__ void __launch_bounds__(NTHR, 1)
lstm_decode_kernel(const float* __restrict__ enc,
                   const float* __restrict__ finalx,
                   const float* __restrict__ W_enc,
                   const float* __restrict__ b_enc,
                   const float* __restrict__ W_red,
                   const float* __restrict__ b_red,
                   float* __restrict__ out)
{
    extern __shared__ char smem[];
    float* shv    = (float*)(smem + VOFF);
    float* shu    = (float*)(smem + UOFF);
    float* shwred = (float*)(smem + WREDOFF);
    float* shy    = (float*)(smem + YOFF);
    float* shpart = (float*)(smem + PARTOFF);

    const int tid = threadIdx.x;
    const int w   = tid >> 5;
    const int l   = tid & 31;
    const int rg  = w >> 2;
    const int q   = w & 3;
    const int row0 = blockIdx.x * MROWS;

    for (int i = tid; i < GD; i += NTHR) { shv[i] = g_v[i]; shu[i] = g_u[i]; }
    for (int i = tid; i < HD; i += NTHR) shwred[i] = W_red[i];
    if (tid < MROWS) shy[tid] = finalx[row0 + tid];
    const float bred = __ldg(b_red);

    // ---- h0 = enc @ W_enc + b_enc  ([64,512]@[512,256], scalar fp32) ----
    {
        float* senc = (float*)(smem + WBOFF);            // [64][32]
        float* swe  = (float*)(smem + WBOFF + 8192);     // [32][256]
        float a[4][8];
        #pragma unroll
        for (int r = 0; r < 4; ++r)
            #pragma unroll
            for (int c = 0; c < 8; ++c) a[r][c] = 0.f;

        for (int k0 = 0; k0 < ENCD; k0 += 32) {
            __syncthreads();
            { int r = tid >> 3, c4 = (tid & 7) * 4;
              *(float4*)(senc + r * 32 + c4) =
                  *(const float4*)(enc + (size_t)(row0 + r) * ENCD + k0 + c4); }
            #pragma unroll
            for (int s = 0; s < 4; ++s) {
                int slot = tid + s * NTHR;
                int kk = slot >> 6, c4 = (slot & 63) * 4;
                *(float4*)(swe + kk * 256 + c4) =
                    *(const float4*)(W_enc + (size_t)(k0 + kk) * HD + c4);
            }
            __syncthreads();
            #pragma unroll
            for (int kk = 0; kk < 32; ++kk) {
                float av[4];
                #pragma unroll
                for (int r = 0; r < 4; ++r) av[r] = senc[(4 * w + r) * 32 + kk];
                float4 b0 = *(const float4*)(swe + kk * 256 + l * 8);
                float4 b1 = *(const float4*)(swe + kk * 256 + l * 8 + 4);
                #pragma unroll
                for (int r = 0; r < 4; ++r) {
                    a[r][0] += av[r] * b0.x; a[r][1] += av[r] * b0.y;
                    a[r][2] += av[r] * b0.z; a[r][3] += av[r] * b0.w;
                    a[r][4] += av[r] * b1.x; a[r][5] += av[r] * b1.y;
                    a[r][6] += av[r] * b1.z; a[r][7] += av[r] * b1.w;
                }
            }
        }
        __syncthreads();   // swe reads done before wbuf reuse below
        __nv_bfloat16* hh = (__nv_bfloat16*)(smem);
        __nv_bfloat16* hl = (__nv_bfloat16*)(smem + HBYTES);
        #pragma unroll
        for (int r = 0; r < 4; ++r)
            #pragma unroll
            for (int c = 0; c < 8; ++c) {
                float val = a[r][c] + __ldg(b_enc + l * 8 + c);
                __nv_bfloat16 hi = __float2bfloat16(val);
                hh[(4 * w + r) * HROW + l * 8 + c] = hi;
                hl[(4 * w + r) * HROW + l * 8 + c] =
                    __float2bfloat16(val - __bfloat162float(hi));
            }
    }

    // prologue: stage W chunk 0
    stage_w(smem, 0, tid);
    asm volatile("cp.async.commit_group;");

    const unsigned smem_sh = (unsigned)__cvta_generic_to_shared(smem);
    // A (h) ldmatrix address: row = rg*16 + (l&15), k-half = l>>4
    const unsigned a_off = (rg * 16 + (l & 15)) * HROWB + (l >> 4) * 16;
    // B (W) ldmatrix address within a version buffer: nrow = q*16 + (l&7) + ((l>>4)<<3)
    const unsigned b_off = (q * 16 + (l & 7) + ((l >> 4) << 3)) * WROWB + ((l >> 3) & 1) * 16;
    const int r0 = rg * 16 + (l >> 2);
    const int r1 = r0 + 8;

    float cst[4][2][2][2];
    #pragma unroll
    for (int p = 0; p < 4; ++p)
        #pragma unroll
        for (int j = 0; j < 2; ++j) {
            cst[p][j][0][0] = 0.f; cst[p][j][0][1] = 0.f;
            cst[p][j][1][0] = 0.f; cst[p][j][1][1] = 0.f;
        }

    for (int t = 0; t < TSTEPS; ++t) {
        const unsigned hcur = smem_sh + (unsigned)(t & 1) * (2 * HBYTES);
        const unsigned ahib = hcur + a_off;
        const unsigned alob = hcur + HBYTES + a_off;
        __nv_bfloat16* hn_hi = (__nv_bfloat16*)(smem + ((t + 1) & 1) * (2 * HBYTES));
        __nv_bfloat16* hn_lo = (__nv_bfloat16*)(smem + ((t + 1) & 1) * (2 * HBYTES) + HBYTES);
        float yd0 = 0.f, yd1 = 0.f;

        #pragma unroll
        for (int p = 0; p < 4; ++p) {
            float acc[4][2][4];
            #pragma unroll
            for (int g = 0; g < 4; ++g)
                #pragma unroll
                for (int j = 0; j < 2; ++j) {
                    acc[g][j][0] = 0.f; acc[g][j][1] = 0.f;
                    acc[g][j][2] = 0.f; acc[g][j][3] = 0.f;
                }

            #pragma unroll 1
            for (int kc = 0; kc < 8; ++kc) {
                int c = p * 8 + kc;
                stage_w(smem, (c + 1) & 31, tid);
                asm volatile("cp.async.commit_group;");
                asm volatile("cp.async.wait_group 1;");
                __syncthreads();                         // chunk c visible to all

                unsigned wb = smem_sh + WBOFF + (unsigned)(kc & 1) * (2 * WBUFSZ);
                #pragma unroll
                for (int s = 0; s < 2; ++s) {
                    unsigned ahi[4], alo[4];
                    unsigned ak = (unsigned)(kc * 64 + s * 32);
                    ldm_x4(ahi, ahib + ak);
                    ldm_x4(alo, alob + ak);
                    #pragma unroll
                    for (int g = 0; g < 4; ++g) {
                        unsigned bhi[4], blo[4];
                        unsigned baddr = wb + (unsigned)(g * 64 * WROWB) + b_off + s * 32;
                        ldm_x4(bhi, baddr);
                        ldm_x4(blo, baddr + WBUFSZ);
                        mma_bf16(acc[g][0], ahi, bhi + 0);
                        mma_bf16(acc[g][1], ahi, bhi + 2);
                        mma_bf16(acc[g][0], ahi, blo + 0);
                        mma_bf16(acc[g][1], ahi, blo + 2);
                        mma_bf16(acc[g][0], alo, bhi + 0);
                        mma_bf16(acc[g][1], alo, bhi + 2);
                    }
                }
                __syncthreads();                         // consumption done before restage
            }

            // ---- epilogue for pass p (warp-local gates) ----
            float yp0 = shy[r0], yp1 = shy[r1];
            #pragma unroll
            for (int j = 0; j < 2; ++j)
                #pragma unroll
                for (int cp = 0; cp < 2; ++cp) {
                    int hcol = p * 64 + q * 16 + j * 8 + (l & 3) * 2 + cp;
                    float vi = shv[hcol],          ui = shu[hcol];
                    float vf = shv[HD + hcol],     uf = shu[HD + hcol];
                    float vc = shv[2 * HD + hcol], uc = shu[2 * HD + hcol];
                    float vo = shv[3 * HD + hcol], uo = shu[3 * HD + hcol];
                    float wr = shwred[hcol];
                    #pragma unroll
                    for (int rh = 0; rh < 2; ++rh) {
                        float yy = rh ? yp1 : yp0;
                        int di = rh * 2 + cp;
                        float gi = acc[0][j][di] + yy * vi + ui;
                        float gf = acc[1][j][di] + yy * vf + uf;
                        float gc = acc[2][j][di] + yy * vc + uc;
                        float go = acc[3][j][di] + yy * vo + uo;
                        float cn = sigmoidf_(gf) * cst[p][j][rh][cp]
                                 + sigmoidf_(gi) * tanh_fast(gc);
                        float hn = sigmoidf_(go) * tanh_fast(cn);
                        cst[p][j][rh][cp] = cn;
                        int r = rh ? r1 : r0;
                        __nv_bfloat16 hb = __float2bfloat16(hn);
                        hn_hi[r * HROW + hcol] = hb;
                        hn_lo[r * HROW + hcol] =
                            __float2bfloat16(hn - __bfloat162float(hb));
                        if (rh) yd1 += hn * wr; else yd0 += hn * wr;
                    }
                }
        }

        // ---- y = h_new @ w_red + b_red ----
        yd0 += __shfl_xor_sync(0xffffffffu, yd0, 1);
        yd0 += __shfl_xor_sync(0xffffffffu, yd0, 2);
        yd1 += __shfl_xor_sync(0xffffffffu, yd1, 1);
        yd1 += __shfl_xor_sync(0xffffffffu, yd1, 2);
        if ((l & 3) == 0) {
            shpart[r0 * 4 + q] = yd0;
            shpart[r1 * 4 + q] = yd1;
        }
        __syncthreads();
        if (tid < MROWS) {
            float y = shpart[tid * 4] + shpart[tid * 4 + 1]
                    + shpart[tid * 4 + 2] + shpart[tid * 4 + 3] + bred;
            shy[tid] = y;
            out[(size_t)(row0 + tid) * TSTEPS + t] = y;
        }
        // next step's chunk-0 __syncthreads orders shy/h writes before reads
    }
    asm volatile("cp.async.wait_group 0;");
}

extern "C" void kernel_launch(void* const* d_in, const int* in_sizes, int n_in,
                              void* d_out, int out_size) {
    const float* enc    = (const float*)d_in[0];
    const float* finalx = (const float*)d_in[1];
    const float* W_emb  = (const float*)d_in[2];
    const float* b_emb  = (const float*)d_in[3];
    const float* W_enc  = (const float*)d_in[4];
    const float* b_enc  = (const float*)d_in[5];
    const float* W_k    = (const float*)d_in[6];
    const float* W_r    = (const float*)d_in[7];
    const float* b_lstm = (const float*)d_in[8];
    const float* W_red  = (const float*)d_in[9];
    const float* b_red  = (const float*)d_in[10];
    float* out = (float*)d_out;

    cudaFuncSetAttribute(lstm_decode_kernel,
                         cudaFuncAttributeMaxDynamicSharedMemorySize, SMEMSZ);

    precompute_vu_kernel<<<1, 1024>>>(W_emb, b_emb, W_k, b_lstm);
    precompute_w_kernel<<<512, 512>>>(W_r);
    lstm_decode_kernel<<<BATCH / MROWS, NTHR, SMEMSZ>>>(
        enc, finalx, W_enc, b_enc, W_red, b_red, out);
}